// round 11
// baseline (speedup 1.0000x reference)
#include <cuda_runtime.h>
#include <math.h>

// NeRF-style renderer: B=1, H=W=200, FOCAL=300, NEAR=2, FAR=6, S=128, F=8.
// SEG=4 threads/pixel, 32 samples each, exact width-4 warp-shuffle combine.
// R10 base (best: 22.8us) + exact cuts:
//  - weight LDS vectorized: float4 color weights (channel-major) + float4
//    density weights + fused (t,dl2) float2 -> 9 vector LDS/sample vs 34 scalar
//  - depth telescoped: sum(wgt) == 1 - prod(T) exactly; per-sample add removed
//  - lb(128,10): reg headroom for float4 transients without spills, no tail
// Output: color_map [200*200*3] then depth_map [200*200] (fp32).

#define H 200
#define W 200
#define NPIX (H * W)
#define S 128
#define F 8
#define SEG 4
#define SPT (S / SEG)          // 32
#define FOCAL 300.0f
#define NEARP 2.0f
#define FARP 6.0f
#define L2E 1.4426950408889634f

__device__ __forceinline__ float ex2f(float x) {
    float r; asm("ex2.approx.ftz.f32 %0, %1;" : "=f"(r) : "f"(x)); return r;
}
__device__ __forceinline__ float rcpf(float x) {
    float r; asm("rcp.approx.ftz.f32 %0, %1;" : "=f"(r) : "f"(x)); return r;
}

__global__ __launch_bounds__(128, 10)
void render_kernel(const float* __restrict__ positions,
                   const float* __restrict__ forwards,
                   const float* __restrict__ ups,
                   const float* __restrict__ normal,
                   const float* __restrict__ Wf,
                   const float* __restrict__ bf,
                   const float* __restrict__ Wd,
                   const float* __restrict__ bd,
                   const float* __restrict__ Wc,
                   const float* __restrict__ bc,
                   float* __restrict__ out)
{
    // ---- shared staging ----
    // sample s = q*SPT + i lives at slot i*SEG + q.
    __shared__ float2 s_td[S];         // (t, -delta_raw*log2(e))
    __shared__ float4 s_wd4[2];        // Wd feature part, features 0-3 / 4-7
    __shared__ float4 s_wc4[3][2];     // -log2(e)*Wc_feat, channel-major
    __shared__ float  s_Wf[3][F];
    __shared__ float  s_cam[12];       // right(3), up(3), fwd(3), pos(3)
    __shared__ float  s_Wd3[3];
    __shared__ float  s_negWc3[3][3];  // -log2(e) * Wc_dir
    __shared__ float  s_negbc[3];      // -log2(e) * bc
    __shared__ float  s_bf[F];
    __shared__ float  s_bd;

    const int tid = threadIdx.x;

    if (tid < S) {
        float n0 = normal[tid];
        int xi = (tid % SPT) * SEG + (tid / SPT);   // transposed slot
        float t = NEARP + n0 * (FARP - NEARP);
        float dl = (tid < S - 1) ? (normal[tid + 1] - n0) * (FARP - NEARP)
                                 : 1e10f;
        s_td[xi] = make_float2(t, -dl * L2E);
    }
    if (tid < 24) s_Wf[tid / F][tid % F] = Wf[tid];
    if (tid >= 32 && tid < 32 + F) {
        int j = tid - 32;
        reinterpret_cast<float*>(s_wd4)[j] = Wd[3 + j];
        s_bf[j] = bf[j];
    }
    if (tid >= 40 && tid < 40 + 24) {
        int k = tid - 40;            // k = c*8 + j (channel-major flat layout)
        int c = k / 8, j = k % 8;
        reinterpret_cast<float*>(s_wc4)[k] = -L2E * Wc[(3 + j) * 3 + c];
    }
    if (tid == 0) {
        float ux = ups[0], uy = ups[1], uz = ups[2];
        float fx = forwards[0], fy = forwards[1], fz = forwards[2];
        s_cam[0] = uy * fz - uz * fy;
        s_cam[1] = uz * fx - ux * fz;
        s_cam[2] = ux * fy - uy * fx;
        s_cam[3] = ux; s_cam[4] = uy; s_cam[5] = uz;
        s_cam[6] = fx; s_cam[7] = fy; s_cam[8] = fz;
        s_cam[9] = positions[0]; s_cam[10] = positions[1]; s_cam[11] = positions[2];
        s_Wd3[0] = Wd[0]; s_Wd3[1] = Wd[1]; s_Wd3[2] = Wd[2];
        s_bd = bd[0];
        #pragma unroll
        for (int j = 0; j < 3; j++) {
            s_negbc[j] = -L2E * bc[j];
            #pragma unroll
            for (int i = 0; i < 3; i++) s_negWc3[j][i] = -L2E * Wc[j * 3 + i];
        }
    }
    __syncthreads();

    const int gtid = blockIdx.x * blockDim.x + tid;   // 160,000 threads
    const int pix = gtid >> 2;
    const int q = gtid & 3;

    const int h = pix / W;
    const int w = pix - h * W;

    const float a = ((float)h - (H * 0.5f - 0.5f)) * (1.0f / FOCAL);
    const float b = -((float)w - (W * 0.5f - 0.5f)) * (1.0f / FOCAL);

    const float dx = a * s_cam[0] + b * s_cam[3] + s_cam[6];
    const float dy = a * s_cam[1] + b * s_cam[4] + s_cam[7];
    const float dz = a * s_cam[2] + b * s_cam[5] + s_cam[8];
    const float dn = sqrtf(dx * dx + dy * dy + dz * dz);

    const float px = s_cam[9], py = s_cam[10], pz = s_cam[11];

    // per-pixel projections (hoisted out of the sample loop)
    float dirF[F], baseF[F];
    #pragma unroll
    for (int j = 0; j < F; j++) {
        dirF[j]  = dx * s_Wf[0][j] + dy * s_Wf[1][j] + dz * s_Wf[2][j];
        baseF[j] = px * s_Wf[0][j] + py * s_Wf[1][j] + pz * s_Wf[2][j] + s_bf[j];
    }
    const float dird  = dx * s_Wd3[0] + dy * s_Wd3[1] + dz * s_Wd3[2];
    const float based = px * s_Wd3[0] + py * s_Wd3[1] + pz * s_Wd3[2] + s_bd;

    const float nb0 = dx * s_negWc3[0][0] + dy * s_negWc3[1][0] + dz * s_negWc3[2][0] + s_negbc[0];
    const float nb1 = dx * s_negWc3[0][1] + dy * s_negWc3[1][1] + dz * s_negWc3[2][1] + s_negbc[1];
    const float nb2 = dx * s_negWc3[0][2] + dy * s_negWc3[1][2] + dz * s_negWc3[2][2] + s_negbc[2];

    // ---- local segment compositing (T starts at 1) ----
    float T = 1.0f;
    float c0 = 0.0f, c1 = 0.0f, c2 = 0.0f;

    const float2* td = s_td + q;

    #pragma unroll 4
    for (int i = 0; i < SPT; i++) {
        const float2 tdl = td[i * SEG];
        const float t = tdl.x;

        float f[F];
        #pragma unroll
        for (int j = 0; j < F; j++)
            f[j] = fmaxf(fmaf(t, dirF[j], baseF[j]), 0.0f);

        // density: vector weight loads
        float d = fmaf(t, dird, based);
        {
            const float4 wA = s_wd4[0], wB = s_wd4[1];
            d = fmaf(f[0], wA.x, d); d = fmaf(f[1], wA.y, d);
            d = fmaf(f[2], wA.z, d); d = fmaf(f[3], wA.w, d);
            d = fmaf(f[4], wB.x, d); d = fmaf(f[5], wB.y, d);
            d = fmaf(f[6], wB.z, d); d = fmaf(f[7], wB.w, d);
        }
        d = fmaxf(d, 0.0f);

        // e = exp(-dens*delta*dn) = ex2(d * dl2 * dn)
        const float e  = ex2f(d * (tdl.y * dn));
        const float Tn = T * e;
        const float wgt = T - Tn;
        T = Tn;

        // colors: per-channel vector weight loads + sigmoid (arg pre-scaled by -log2e)
        {
            const float4 wA = s_wc4[0][0], wB = s_wc4[0][1];
            float x = nb0;
            x = fmaf(f[0], wA.x, x); x = fmaf(f[1], wA.y, x);
            x = fmaf(f[2], wA.z, x); x = fmaf(f[3], wA.w, x);
            x = fmaf(f[4], wB.x, x); x = fmaf(f[5], wB.y, x);
            x = fmaf(f[6], wB.z, x); x = fmaf(f[7], wB.w, x);
            c0 = fmaf(wgt, rcpf(1.0f + ex2f(x)), c0);
        }
        {
            const float4 wA = s_wc4[1][0], wB = s_wc4[1][1];
            float x = nb1;
            x = fmaf(f[0], wA.x, x); x = fmaf(f[1], wA.y, x);
            x = fmaf(f[2], wA.z, x); x = fmaf(f[3], wA.w, x);
            x = fmaf(f[4], wB.x, x); x = fmaf(f[5], wB.y, x);
            x = fmaf(f[6], wB.z, x); x = fmaf(f[7], wB.w, x);
            c1 = fmaf(wgt, rcpf(1.0f + ex2f(x)), c1);
        }
        {
            const float4 wA = s_wc4[2][0], wB = s_wc4[2][1];
            float x = nb2;
            x = fmaf(f[0], wA.x, x); x = fmaf(f[1], wA.y, x);
            x = fmaf(f[2], wA.z, x); x = fmaf(f[3], wA.w, x);
            x = fmaf(f[4], wB.x, x); x = fmaf(f[5], wB.y, x);
            x = fmaf(f[6], wB.z, x); x = fmaf(f[7], wB.w, x);
            c2 = fmaf(wgt, rcpf(1.0f + ex2f(x)), c2);
        }
    }

    // ---- segmented combine across the 4 threads of this pixel ----
    // depth telescopes: sum of weights over the whole ray = 1 - prod(T_q)
    const unsigned mask = 0xFFFFFFFFu;
    const float T0 = __shfl_sync(mask, T, 0, 4);
    const float T1 = __shfl_sync(mask, T, 1, 4);
    const float T2 = __shfl_sync(mask, T, 2, 4);
    const float T3 = __shfl_sync(mask, T, 3, 4);
    float p = 1.0f;
    if (q > 0) p *= T0;
    if (q > 1) p *= T1;
    if (q > 2) p *= T2;
    c0 *= p; c1 *= p; c2 *= p;

    #pragma unroll
    for (int off = 1; off < SEG; off <<= 1) {
        c0 += __shfl_xor_sync(mask, c0, off, 4);
        c1 += __shfl_xor_sync(mask, c1, off, 4);
        c2 += __shfl_xor_sync(mask, c2, off, 4);
    }

    if (q == 0) {
        out[pix * 3 + 0] = c0;
        out[pix * 3 + 1] = c1;
        out[pix * 3 + 2] = c2;
        out[NPIX * 3 + pix] = 1.0f - ((T0 * T1) * (T2 * T3));
    }
}

extern "C" void kernel_launch(void* const* d_in, const int* in_sizes, int n_in,
                              void* d_out, int out_size)
{
    const float* positions = (const float*)d_in[0];
    const float* forwards  = (const float*)d_in[1];
    const float* ups       = (const float*)d_in[2];
    const float* normal    = (const float*)d_in[3];
    const float* Wf        = (const float*)d_in[4];
    const float* bf        = (const float*)d_in[5];
    const float* Wd        = (const float*)d_in[6];
    const float* bd        = (const float*)d_in[7];
    const float* Wc        = (const float*)d_in[8];
    const float* bc        = (const float*)d_in[9];
    float* out = (float*)d_out;

    const int threads = 128;
    const int blocks = (NPIX * SEG) / threads;   // 1250
    render_kernel<<<blocks, threads>>>(positions, forwards, ups, normal,
                                       Wf, bf, Wd, bd, Wc, bc, out);
}

// round 13
// speedup vs baseline: 1.1997x; 1.1997x over previous
#include <cuda_runtime.h>
#include <math.h>

// NeRF-style renderer: B=1, H=W=200, FOCAL=300, NEAR=2, FAR=6, S=128, F=8.
// SEG=4 threads/pixel, 32 samples each, exact width-4 warp-shuffle combine.
// R10 structure (32-reg regime, weights streamed from shared in-loop).
// Deltas vs R10:
//  - sigmoid via tanh.approx: g = 0.5 + 0.5*tanh(z/2); color weights staged
//    pre-scaled by +0.5 so the matvec yields z/2 directly. The 0.5*sum(wgt)
//    term is recovered exactly in the epilogue via transmittance telescoping.
//  - depth telescoped: sum(wgt) == 1 - prod(T_q) exactly.
// Output: color_map [200*200*3] then depth_map [200*200] (fp32).

#define H 200
#define W 200
#define NPIX (H * W)
#define S 128
#define F 8
#define SEG 4
#define SPT (S / SEG)          // 32
#define FOCAL 300.0f
#define NEARP 2.0f
#define FARP 6.0f
#define L2E 1.4426950408889634f

__device__ __forceinline__ float ex2f(float x) {
    float r; asm("ex2.approx.ftz.f32 %0, %1;" : "=f"(r) : "f"(x)); return r;
}
__device__ __forceinline__ float tanhf_hw(float x) {
    float r; asm("tanh.approx.f32 %0, %1;" : "=f"(r) : "f"(x)); return r;
}

__global__ __launch_bounds__(128, 16)
void render_kernel(const float* __restrict__ positions,
                   const float* __restrict__ forwards,
                   const float* __restrict__ ups,
                   const float* __restrict__ normal,
                   const float* __restrict__ Wf,
                   const float* __restrict__ bf,
                   const float* __restrict__ Wd,
                   const float* __restrict__ bd,
                   const float* __restrict__ Wc,
                   const float* __restrict__ bc,
                   float* __restrict__ out)
{
    // ---- shared staging ----
    // sample s = q*SPT + i lives at slot i*SEG + q.
    __shared__ float s_t[S];
    __shared__ float s_dl2[S];         // -delta_raw * log2(e)
    __shared__ float s_Wf[3][F];
    __shared__ float s_WdF[F];
    __shared__ float s_WcFh[F][3];     // +0.5 * Wc_feat  (tanh half-arg)
    __shared__ float s_cam[12];        // right(3), up(3), fwd(3), pos(3)
    __shared__ float s_Wd3[3];
    __shared__ float s_Wc3h[3][3];     // +0.5 * Wc_dir
    __shared__ float s_bch[3];         // +0.5 * bc
    __shared__ float s_bf[F];
    __shared__ float s_bd;

    const int tid = threadIdx.x;

    if (tid < S) {
        float n0 = normal[tid];
        int xi = (tid % SPT) * SEG + (tid / SPT);   // transposed slot
        s_t[xi] = NEARP + n0 * (FARP - NEARP);
        float dl = (tid < S - 1) ? (normal[tid + 1] - n0) * (FARP - NEARP)
                                 : 1e10f;
        s_dl2[xi] = -dl * L2E;
    }
    if (tid < 24) s_Wf[tid / F][tid % F] = Wf[tid];
    if (tid >= 32 && tid < 32 + F) {
        int j = tid - 32;
        s_WdF[j] = Wd[3 + j];
        s_bf[j] = bf[j];
    }
    if (tid >= 40 && tid < 40 + 24) {
        int k = tid - 40;
        s_WcFh[k / 3][k % 3] = 0.5f * Wc[(3 + k / 3) * 3 + (k % 3)];
    }
    if (tid == 0) {
        float ux = ups[0], uy = ups[1], uz = ups[2];
        float fx = forwards[0], fy = forwards[1], fz = forwards[2];
        s_cam[0] = uy * fz - uz * fy;
        s_cam[1] = uz * fx - ux * fz;
        s_cam[2] = ux * fy - uy * fx;
        s_cam[3] = ux; s_cam[4] = uy; s_cam[5] = uz;
        s_cam[6] = fx; s_cam[7] = fy; s_cam[8] = fz;
        s_cam[9] = positions[0]; s_cam[10] = positions[1]; s_cam[11] = positions[2];
        s_Wd3[0] = Wd[0]; s_Wd3[1] = Wd[1]; s_Wd3[2] = Wd[2];
        s_bd = bd[0];
        #pragma unroll
        for (int j = 0; j < 3; j++) {
            s_bch[j] = 0.5f * bc[j];
            #pragma unroll
            for (int i = 0; i < 3; i++) s_Wc3h[j][i] = 0.5f * Wc[j * 3 + i];
        }
    }
    __syncthreads();

    const int gtid = blockIdx.x * blockDim.x + tid;   // 160,000 threads
    const int pix = gtid >> 2;
    const int q = gtid & 3;

    const int h = pix / W;
    const int w = pix - h * W;

    const float a = ((float)h - (H * 0.5f - 0.5f)) * (1.0f / FOCAL);
    const float b = -((float)w - (W * 0.5f - 0.5f)) * (1.0f / FOCAL);

    const float dx = a * s_cam[0] + b * s_cam[3] + s_cam[6];
    const float dy = a * s_cam[1] + b * s_cam[4] + s_cam[7];
    const float dz = a * s_cam[2] + b * s_cam[5] + s_cam[8];
    const float dn = sqrtf(dx * dx + dy * dy + dz * dz);

    const float px = s_cam[9], py = s_cam[10], pz = s_cam[11];

    // per-pixel projections (hoisted out of the sample loop)
    float dirF[F], baseF[F];
    #pragma unroll
    for (int j = 0; j < F; j++) {
        dirF[j]  = dx * s_Wf[0][j] + dy * s_Wf[1][j] + dz * s_Wf[2][j];
        baseF[j] = px * s_Wf[0][j] + py * s_Wf[1][j] + pz * s_Wf[2][j] + s_bf[j];
    }
    const float dird  = dx * s_Wd3[0] + dy * s_Wd3[1] + dz * s_Wd3[2];
    const float based = px * s_Wd3[0] + py * s_Wd3[1] + pz * s_Wd3[2] + s_bd;

    // half-scaled color bias terms (dir part + bc), i.e. z/2 seeds
    const float hb0 = dx * s_Wc3h[0][0] + dy * s_Wc3h[1][0] + dz * s_Wc3h[2][0] + s_bch[0];
    const float hb1 = dx * s_Wc3h[0][1] + dy * s_Wc3h[1][1] + dz * s_Wc3h[2][1] + s_bch[1];
    const float hb2 = dx * s_Wc3h[0][2] + dy * s_Wc3h[1][2] + dz * s_Wc3h[2][2] + s_bch[2];

    // ---- local segment compositing ----
    // Track Th = 0.5*T (init 0.5): wh = Th - Th*e = 0.5*wgt, used directly with
    // tanh; the +0.5*sum(wgt) sigmoid completion = (0.5 - Th_end), added in the
    // epilogue. Exact.
    float Th = 0.5f;
    float c0 = 0.0f, c1 = 0.0f, c2 = 0.0f;

    #pragma unroll 4
    for (int i = 0; i < SPT; i++) {
        const int xi = i * SEG + q;
        const float t = s_t[xi];

        float f[F];
        #pragma unroll
        for (int j = 0; j < F; j++)
            f[j] = fmaxf(fmaf(t, dirF[j], baseF[j]), 0.0f);

        float d = fmaf(t, dird, based);
        #pragma unroll
        for (int j = 0; j < F; j++)
            d = fmaf(f[j], s_WdF[j], d);
        d = fmaxf(d, 0.0f);

        // e = exp(-dens*delta*dn) = ex2(d * dl2 * dn)
        const float e   = ex2f(d * (s_dl2[xi] * dn));
        const float Thn = Th * e;
        const float wh  = Th - Thn;       // 0.5 * wgt
        Th = Thn;

        float x0 = hb0, x1 = hb1, x2 = hb2;
        #pragma unroll
        for (int j = 0; j < F; j++) {
            x0 = fmaf(f[j], s_WcFh[j][0], x0);
            x1 = fmaf(f[j], s_WcFh[j][1], x1);
            x2 = fmaf(f[j], s_WcFh[j][2], x2);
        }
        // sigmoid(z) = 0.5 + 0.5*tanh(z/2);  x_c == z/2 by staging
        c0 = fmaf(wh, tanhf_hw(x0), c0);
        c1 = fmaf(wh, tanhf_hw(x1), c1);
        c2 = fmaf(wh, tanhf_hw(x2), c2);
    }

    // complete the sigmoid's +0.5 term: sum(0.5*wgt) = 0.5 - Th
    const float half_wsum = 0.5f - Th;
    c0 += half_wsum; c1 += half_wsum; c2 += half_wsum;
    const float T = 2.0f * Th;

    // ---- segmented combine across the 4 threads of this pixel ----
    const unsigned mask = 0xFFFFFFFFu;
    const float T0 = __shfl_sync(mask, T, 0, 4);
    const float T1 = __shfl_sync(mask, T, 1, 4);
    const float T2 = __shfl_sync(mask, T, 2, 4);
    const float T3 = __shfl_sync(mask, T, 3, 4);
    float p = 1.0f;
    if (q > 0) p *= T0;
    if (q > 1) p *= T1;
    if (q > 2) p *= T2;
    c0 *= p; c1 *= p; c2 *= p;

    #pragma unroll
    for (int off = 1; off < SEG; off <<= 1) {
        c0 += __shfl_xor_sync(mask, c0, off, 4);
        c1 += __shfl_xor_sync(mask, c1, off, 4);
        c2 += __shfl_xor_sync(mask, c2, off, 4);
    }

    if (q == 0) {
        out[pix * 3 + 0] = c0;
        out[pix * 3 + 1] = c1;
        out[pix * 3 + 2] = c2;
        out[NPIX * 3 + pix] = 1.0f - ((T0 * T1) * (T2 * T3));
    }
}

extern "C" void kernel_launch(void* const* d_in, const int* in_sizes, int n_in,
                              void* d_out, int out_size)
{
    const float* positions = (const float*)d_in[0];
    const float* forwards  = (const float*)d_in[1];
    const float* ups       = (const float*)d_in[2];
    const float* normal    = (const float*)d_in[3];
    const float* Wf        = (const float*)d_in[4];
    const float* bf        = (const float*)d_in[5];
    const float* Wd        = (const float*)d_in[6];
    const float* bd        = (const float*)d_in[7];
    const float* Wc        = (const float*)d_in[8];
    const float* bc        = (const float*)d_in[9];
    float* out = (float*)d_out;

    const int threads = 128;
    const int blocks = (NPIX * SEG) / threads;   // 1250
    render_kernel<<<blocks, threads>>>(positions, forwards, ups, normal,
                                       Wf, bf, Wd, bd, Wc, bc, out);
}